// round 1
// baseline (speedup 1.0000x reference)
#include <cuda_runtime.h>
#include <math.h>

// Problem constants
#define Bq 2
#define Nn 2048
#define Cc 1024
#define Hh 16
#define Dd 64
static __device__ __constant__ float SCALE = 0.125f;  // D^-0.5

// Scratch: q,k,v,attn-out in [B,H,N,D] layout (16.78 MB each)
__device__ float g_q [(size_t)Bq*Hh*Nn*Dd];
__device__ float g_k [(size_t)Bq*Hh*Nn*Dd];
__device__ float g_v [(size_t)Bq*Hh*Nn*Dd];
__device__ float g_ao[(size_t)Bq*Hh*Nn*Dd];

// ---------------------------------------------------------------------------
// GEMM: out[M,NC] = A[M,K] @ W[NC,K]^T + bias
// MODE 0: A = x, NC=3072, epilogue scatters into g_q/g_k/g_v ([B,H,N,D])
// MODE 1: A = g_ao (reinterpreted [4096,1024]), NC=1024, writes d_out
// 128x128 tile, BK=16, 8x8 per thread, 256 threads.
// ---------------------------------------------------------------------------
template<int MODE>
__global__ __launch_bounds__(256, 2)
void gemm_kernel(const float* __restrict__ Ain, const float* __restrict__ W,
                 const float* __restrict__ bias, float* __restrict__ out)
{
    constexpr int K  = 1024;
    constexpr int NC = (MODE == 0) ? 3072 : 1024;
    const float* A = (MODE == 0) ? Ain : g_ao;

    __shared__ float As[16][128];
    __shared__ float Bs[16][128];

    const int tid = threadIdx.x;
    const int tr  = tid >> 4;   // 0..15
    const int tc  = tid & 15;   // 0..15

    const int rowBase = blockIdx.y * 128;
    const int colBase = blockIdx.x * 128;

    float acc[8][8];
    #pragma unroll
    for (int i = 0; i < 8; i++)
        #pragma unroll
        for (int j = 0; j < 8; j++) acc[i][j] = 0.f;

    for (int kt = 0; kt < K; kt += 16) {
        // Load A tile (128 rows x 16 cols), store transposed As[k][m]
        #pragma unroll
        for (int i = tid; i < 512; i += 256) {
            int r = i >> 2, c4 = i & 3;
            float4 v = *(const float4*)(A + (size_t)(rowBase + r) * K + kt + c4 * 4);
            As[c4*4+0][r] = v.x; As[c4*4+1][r] = v.y;
            As[c4*4+2][r] = v.z; As[c4*4+3][r] = v.w;
        }
        // Load W tile (128 rows x 16 cols), store transposed Bs[k][n]
        #pragma unroll
        for (int i = tid; i < 512; i += 256) {
            int r = i >> 2, c4 = i & 3;
            float4 v = *(const float4*)(W + (size_t)(colBase + r) * K + kt + c4 * 4);
            Bs[c4*4+0][r] = v.x; Bs[c4*4+1][r] = v.y;
            Bs[c4*4+2][r] = v.z; Bs[c4*4+3][r] = v.w;
        }
        __syncthreads();

        #pragma unroll
        for (int kk = 0; kk < 16; kk++) {
            float regM[8], regN[8];
            *(float4*)&regM[0] = *(const float4*)&As[kk][tr*8];
            *(float4*)&regM[4] = *(const float4*)&As[kk][tr*8 + 4];
            *(float4*)&regN[0] = *(const float4*)&Bs[kk][tc*8];
            *(float4*)&regN[4] = *(const float4*)&Bs[kk][tc*8 + 4];
            #pragma unroll
            for (int i = 0; i < 8; i++)
                #pragma unroll
                for (int j = 0; j < 8; j++)
                    acc[i][j] += regM[i] * regN[j];
        }
        __syncthreads();
    }

    #pragma unroll
    for (int i = 0; i < 8; i++) {
        const int row = rowBase + tr*8 + i;
        #pragma unroll
        for (int j = 0; j < 8; j++) {
            const int col = colBase + tc*8 + j;
            float val = acc[i][j] + bias[col];
            if (MODE == 0) {
                // col = s*1024 + h*64 + d ; row = b*2048 + n
                int s = col >> 10;
                int h = (col >> 6) & 15;
                int d = col & 63;
                int b = row >> 11;
                int n = row & 2047;
                float* dst = (s == 0) ? g_q : (s == 1) ? g_k : g_v;
                dst[(((size_t)b * Hh + h) * Nn + n) * Dd + d] = val;
            } else {
                out[(size_t)row * NC + col] = val;
            }
        }
    }
}

// ---------------------------------------------------------------------------
// Causal flash attention, fp32. One warp per query row, 8 rows per block.
// Online softmax; K stored transposed in smem (pad 33 -> conflict-free reads).
// Output goes to g_ao in [B,H,N,D]; reinterpreting that buffer as [B,N,C] is
// exactly the reference's no-transpose reshape.
// ---------------------------------------------------------------------------
__global__ __launch_bounds__(256)
void attn_kernel()
{
    __shared__ float Qs[8][64];
    __shared__ float Kt[64][33];   // [d][j], pad 33
    __shared__ float Vs[32][64];   // [j][d]

    const int bh   = blockIdx.x;          // b*H + h
    const int r0   = blockIdx.y * 8;      // first query row of this block
    const int tid  = threadIdx.x;
    const int warp = tid >> 5;
    const int lane = tid & 31;
    const int row  = r0 + warp;           // this warp's query row

    const float* qb = g_q + (size_t)bh * Nn * Dd;
    const float* kb = g_k + (size_t)bh * Nn * Dd;
    const float* vb = g_v + (size_t)bh * Nn * Dd;

    for (int i = tid; i < 8 * 64; i += 256)
        Qs[i >> 6][i & 63] = qb[(size_t)(r0 + (i >> 6)) * Dd + (i & 63)];

    float m = -1e30f, l = 0.f, acc0 = 0.f, acc1 = 0.f;

    const int ntiles = (r0 + 7) / 32 + 1;   // causal: only tiles with j <= r0+7
    for (int t = 0; t < ntiles; t++) {
        const int jbase = t * 32;
        __syncthreads();
        // Load K (transposed) and V tiles: 32 keys x 64 dims each
        #pragma unroll
        for (int i = tid; i < 512; i += 256) {
            int jr = i >> 4, c4 = i & 15;
            const float* kp = kb + (size_t)(jbase + jr) * Dd + c4 * 4;
            float4 kv = *(const float4*)kp;
            Kt[c4*4+0][jr] = kv.x; Kt[c4*4+1][jr] = kv.y;
            Kt[c4*4+2][jr] = kv.z; Kt[c4*4+3][jr] = kv.w;
            const float* vp = vb + (size_t)(jbase + jr) * Dd + c4 * 4;
            *(float4*)&Vs[jr][c4*4] = *(const float4*)vp;
        }
        __syncthreads();

        // score for key j = jbase + lane
        float s = 0.f;
        #pragma unroll
        for (int d = 0; d < 64; d++)
            s += Qs[warp][d] * Kt[d][lane];
        s *= SCALE;
        if (jbase + lane > row) s = -1e30f;   // causal mask

        // online softmax update (warp-wide)
        float tmax = s;
        #pragma unroll
        for (int o = 16; o; o >>= 1)
            tmax = fmaxf(tmax, __shfl_xor_sync(0xffffffffu, tmax, o));
        float nm    = fmaxf(m, tmax);
        float p     = __expf(s - nm);
        float alpha = __expf(m - nm);
        float psum  = p;
        #pragma unroll
        for (int o = 16; o; o >>= 1)
            psum += __shfl_xor_sync(0xffffffffu, psum, o);
        l = l * alpha + psum;
        acc0 *= alpha;
        acc1 *= alpha;

        // acc[d] += sum_j p_j * V[j][d]; lane owns d = lane and lane+32
        #pragma unroll
        for (int jj = 0; jj < 32; jj++) {
            float pj = __shfl_sync(0xffffffffu, p, jj);
            acc0 += pj * Vs[jj][lane];
            acc1 += pj * Vs[jj][lane + 32];
        }
        m = nm;
    }

    const float inv = 1.f / l;
    float* ob = g_ao + ((size_t)bh * Nn + row) * Dd;
    ob[lane]      = acc0 * inv;
    ob[lane + 32] = acc1 * inv;
}

// ---------------------------------------------------------------------------
extern "C" void kernel_launch(void* const* d_in, const int* in_sizes, int n_in,
                              void* d_out, int out_size)
{
    const float* x      = (const float*)d_in[0];
    // d_in[1] = attention_mask: exactly causal tril, encoded in the kernel — unused
    const float* w_qkv  = (const float*)d_in[2];
    const float* b_qkv  = (const float*)d_in[3];
    const float* w_proj = (const float*)d_in[4];
    const float* b_proj = (const float*)d_in[5];
    float* out = (float*)d_out;

    dim3 g_qkv(3072 / 128, (Bq * Nn) / 128);      // 24 x 32
    gemm_kernel<0><<<g_qkv, 256>>>(x, w_qkv, b_qkv, nullptr);

    dim3 g_att(Bq * Hh, Nn / 8);                  // 32 x 256
    attn_kernel<<<g_att, 256>>>();

    dim3 g_prj(1024 / 128, (Bq * Nn) / 128);      // 8 x 32
    gemm_kernel<1><<<g_prj, 256>>>(nullptr, w_proj, b_proj, out);
}

// round 2
// speedup vs baseline: 1.1585x; 1.1585x over previous
#include <cuda_runtime.h>
#include <math.h>

// Problem constants
#define Bq 2
#define Nn 2048
#define Cc 1024
#define Hh 16
#define Dd 64

// Scratch. Layouts:
//   g_q, g_k : [b][h][d][n]  (TRANSPOSED — written that way by the QKV epilogue)
//   g_v, g_ao: [b][h][n][d]
__device__ float g_q [(size_t)Bq*Hh*Nn*Dd];
__device__ float g_k [(size_t)Bq*Hh*Nn*Dd];
__device__ float g_v [(size_t)Bq*Hh*Nn*Dd];
__device__ float g_ao[(size_t)Bq*Hh*Nn*Dd];

// ---------------------------------------------------------------------------
// GEMM: out[M,NC] = A[M,K] @ W[NC,K]^T + bias
// MODE 0: A = x, NC=3072, epilogue scatters into g_q/g_k (transposed) / g_v
// MODE 1: A = g_ao (reinterpreted [4096,1024]), NC=1024, writes d_out
// ---------------------------------------------------------------------------
template<int MODE>
__global__ __launch_bounds__(256, 2)
void gemm_kernel(const float* __restrict__ Ain, const float* __restrict__ W,
                 const float* __restrict__ bias, float* __restrict__ out)
{
    constexpr int K  = 1024;
    constexpr int NC = (MODE == 0) ? 3072 : 1024;
    const float* A = (MODE == 0) ? Ain : g_ao;

    __shared__ float As[16][128];
    __shared__ float Bs[16][128];

    const int tid = threadIdx.x;
    const int tr  = tid >> 4;
    const int tc  = tid & 15;

    const int rowBase = blockIdx.y * 128;
    const int colBase = blockIdx.x * 128;

    float acc[8][8];
    #pragma unroll
    for (int i = 0; i < 8; i++)
        #pragma unroll
        for (int j = 0; j < 8; j++) acc[i][j] = 0.f;

    for (int kt = 0; kt < K; kt += 16) {
        #pragma unroll
        for (int i = tid; i < 512; i += 256) {
            int r = i >> 2, c4 = i & 3;
            float4 v = *(const float4*)(A + (size_t)(rowBase + r) * K + kt + c4 * 4);
            As[c4*4+0][r] = v.x; As[c4*4+1][r] = v.y;
            As[c4*4+2][r] = v.z; As[c4*4+3][r] = v.w;
        }
        #pragma unroll
        for (int i = tid; i < 512; i += 256) {
            int r = i >> 2, c4 = i & 3;
            float4 v = *(const float4*)(W + (size_t)(colBase + r) * K + kt + c4 * 4);
            Bs[c4*4+0][r] = v.x; Bs[c4*4+1][r] = v.y;
            Bs[c4*4+2][r] = v.z; Bs[c4*4+3][r] = v.w;
        }
        __syncthreads();

        #pragma unroll
        for (int kk = 0; kk < 16; kk++) {
            float regM[8], regN[8];
            *(float4*)&regM[0] = *(const float4*)&As[kk][tr*8];
            *(float4*)&regM[4] = *(const float4*)&As[kk][tr*8 + 4];
            *(float4*)&regN[0] = *(const float4*)&Bs[kk][tc*8];
            *(float4*)&regN[4] = *(const float4*)&Bs[kk][tc*8 + 4];
            #pragma unroll
            for (int i = 0; i < 8; i++)
                #pragma unroll
                for (int j = 0; j < 8; j++)
                    acc[i][j] += regM[i] * regN[j];
        }
        __syncthreads();
    }

    #pragma unroll
    for (int i = 0; i < 8; i++) {
        const int row = rowBase + tr*8 + i;
        #pragma unroll
        for (int j = 0; j < 8; j++) {
            const int col = colBase + tc*8 + j;
            float val = acc[i][j] + bias[col];
            if (MODE == 0) {
                // col = s*1024 + h*64 + d ; row = b*2048 + n
                int s = col >> 10;
                int h = (col >> 6) & 15;
                int d = col & 63;
                int b = row >> 11;
                int n = row & 2047;
                if (s == 0)       // q, transposed [b][h][d][n], pre-scaled
                    g_q[(((size_t)b * Hh + h) * Dd + d) * Nn + n] = val * 0.125f;
                else if (s == 1)  // k, transposed [b][h][d][n]
                    g_k[(((size_t)b * Hh + h) * Dd + d) * Nn + n] = val;
                else              // v, natural [b][h][n][d]
                    g_v[(((size_t)b * Hh + h) * Nn + n) * Dd + d] = val;
            } else {
                out[(size_t)row * NC + col] = val;
            }
        }
    }
}

// ---------------------------------------------------------------------------
// Block-tiled causal flash attention (fp32).
// Block = 64 queries x one (b,h). 256 threads as 16x16; each thread owns a
// 4x4 S/P fragment (rows on tr, keys on tc) and a 4x4 O fragment (dims on tc).
// Q,K read from transposed [d][n] global layout -> conflict-free f4 smem.
// P reuses the K buffer with XOR-swizzled float4 slots.
// ---------------------------------------------------------------------------
__global__ __launch_bounds__(256)
void attn_kernel()
{
    __shared__ float Qt[64 * 64];   // Qt[d][i]
    __shared__ float KP[64 * 64];   // Kt[d][j] during S; swizzled P[i][j] after
    __shared__ float Vs[64 * 64];   // Vs[j][d]

    const int bh  = blockIdx.x;
    const int r0  = ((int)gridDim.y - 1 - (int)blockIdx.y) * 64; // heavy blocks first
    const int tid = threadIdx.x;
    const int tr  = tid >> 4;
    const int tc  = tid & 15;

    const float* qT = g_q + (size_t)bh * Nn * Dd;   // [d][n]
    const float* kT = g_k + (size_t)bh * Nn * Dd;   // [d][n]
    const float* vb = g_v + (size_t)bh * Nn * Dd;   // [n][d]

    // Load Q tile (once per block): Qt[d][i] = qT[d*Nn + r0 + i]
    #pragma unroll
    for (int i = tid; i < 1024; i += 256) {
        int d = i >> 4, c4 = i & 15;
        *(float4*)&Qt[d * 64 + c4 * 4] =
            *(const float4*)(qT + (size_t)d * Nn + r0 + c4 * 4);
    }

    float m[4], l[4], acc[4][4];
    #pragma unroll
    for (int ii = 0; ii < 4; ii++) {
        m[ii] = -1e30f; l[ii] = 0.f;
        #pragma unroll
        for (int dd = 0; dd < 4; dd++) acc[ii][dd] = 0.f;
    }

    const int ntiles = r0 / 64 + 1;
    for (int t = 0; t < ntiles; t++) {
        const int jb = t * 64;
        __syncthreads();
        // Load K (transposed layout -> natural copy) and V tiles
        #pragma unroll
        for (int i = tid; i < 1024; i += 256) {
            int r = i >> 4, c4 = i & 15;
            *(float4*)&KP[r * 64 + c4 * 4] =
                *(const float4*)(kT + (size_t)r * Nn + jb + c4 * 4);
            *(float4*)&Vs[r * 64 + c4 * 4] =
                *(const float4*)(vb + (size_t)(jb + r) * Dd + c4 * 4);
        }
        __syncthreads();

        // S = Q @ K^T (pre-scaled q)
        float s[4][4];
        #pragma unroll
        for (int ii = 0; ii < 4; ii++)
            #pragma unroll
            for (int jj = 0; jj < 4; jj++) s[ii][jj] = 0.f;

        #pragma unroll 8
        for (int d = 0; d < 64; d++) {
            float4 qv = *(const float4*)&Qt[d * 64 + tr * 4];
            float4 kv = *(const float4*)&KP[d * 64 + tc * 4];
            float qm[4] = {qv.x, qv.y, qv.z, qv.w};
            float kn[4] = {kv.x, kv.y, kv.z, kv.w};
            #pragma unroll
            for (int ii = 0; ii < 4; ii++)
                #pragma unroll
                for (int jj = 0; jj < 4; jj++)
                    s[ii][jj] += qm[ii] * kn[jj];
        }

        // Causal mask (only the diagonal tile needs it)
        if (t == ntiles - 1) {
            #pragma unroll
            for (int ii = 0; ii < 4; ii++)
                #pragma unroll
                for (int jj = 0; jj < 4; jj++)
                    if (jb + tc * 4 + jj > r0 + tr * 4 + ii) s[ii][jj] = -1e30f;
        }

        // Online softmax per row (row group = 16 contiguous lanes)
        #pragma unroll
        for (int ii = 0; ii < 4; ii++) {
            float rm = fmaxf(fmaxf(s[ii][0], s[ii][1]), fmaxf(s[ii][2], s[ii][3]));
            #pragma unroll
            for (int o = 8; o; o >>= 1)
                rm = fmaxf(rm, __shfl_xor_sync(0xffffffffu, rm, o));
            float nm = fmaxf(m[ii], rm);
            float al = __expf(m[ii] - nm);
            m[ii] = nm;
            float rs = 0.f;
            #pragma unroll
            for (int jj = 0; jj < 4; jj++) {
                s[ii][jj] = __expf(s[ii][jj] - nm);
                rs += s[ii][jj];
            }
            #pragma unroll
            for (int o = 8; o; o >>= 1)
                rs += __shfl_xor_sync(0xffffffffu, rs, o);
            l[ii] = l[ii] * al + rs;
            #pragma unroll
            for (int dd = 0; dd < 4; dd++) acc[ii][dd] *= al;
        }

        __syncthreads();   // all Kt reads done; KP becomes P
        // Write P with XOR-swizzled float4 slots: P row i, slot (j/4)^(i&15)
        #pragma unroll
        for (int ii = 0; ii < 4; ii++) {
            int row  = tr * 4 + ii;
            int slot = tc ^ (row & 15);
            *(float4*)&KP[row * 64 + slot * 4] =
                make_float4(s[ii][0], s[ii][1], s[ii][2], s[ii][3]);
        }
        __syncthreads();

        // O += P @ V
        #pragma unroll 4
        for (int j4 = 0; j4 < 16; j4++) {
            float4 v0 = *(const float4*)&Vs[(j4 * 4 + 0) * 64 + tc * 4];
            float4 v1 = *(const float4*)&Vs[(j4 * 4 + 1) * 64 + tc * 4];
            float4 v2 = *(const float4*)&Vs[(j4 * 4 + 2) * 64 + tc * 4];
            float4 v3 = *(const float4*)&Vs[(j4 * 4 + 3) * 64 + tc * 4];
            #pragma unroll
            for (int ii = 0; ii < 4; ii++) {
                int row = tr * 4 + ii;
                float4 pv = *(const float4*)&KP[row * 64 + (j4 ^ (row & 15)) * 4];
                acc[ii][0] += pv.x * v0.x + pv.y * v1.x + pv.z * v2.x + pv.w * v3.x;
                acc[ii][1] += pv.x * v0.y + pv.y * v1.y + pv.z * v2.y + pv.w * v3.y;
                acc[ii][2] += pv.x * v0.z + pv.y * v1.z + pv.z * v2.z + pv.w * v3.z;
                acc[ii][3] += pv.x * v0.w + pv.y * v1.w + pv.z * v2.w + pv.w * v3.w;
            }
        }
    }

    // Normalize + store to g_ao [b][h][n][d]
    #pragma unroll
    for (int ii = 0; ii < 4; ii++) {
        const float inv = 1.f / l[ii];
        const int row = r0 + tr * 4 + ii;
        float4 o = make_float4(acc[ii][0] * inv, acc[ii][1] * inv,
                               acc[ii][2] * inv, acc[ii][3] * inv);
        *(float4*)(g_ao + ((size_t)bh * Nn + row) * Dd + tc * 4) = o;
    }
}

// ---------------------------------------------------------------------------
extern "C" void kernel_launch(void* const* d_in, const int* in_sizes, int n_in,
                              void* d_out, int out_size)
{
    const float* x      = (const float*)d_in[0];
    // d_in[1] = attention_mask: exactly causal tril, encoded in the kernel — unused
    const float* w_qkv  = (const float*)d_in[2];
    const float* b_qkv  = (const float*)d_in[3];
    const float* w_proj = (const float*)d_in[4];
    const float* b_proj = (const float*)d_in[5];
    float* out = (float*)d_out;

    dim3 g_qkv(3072 / 128, (Bq * Nn) / 128);      // 24 x 32
    gemm_kernel<0><<<g_qkv, 256>>>(x, w_qkv, b_qkv, nullptr);

    dim3 g_att(Bq * Hh, Nn / 64);                 // 32 x 32
    attn_kernel<<<g_att, 256>>>();

    dim3 g_prj(1024 / 128, (Bq * Nn) / 128);      // 8 x 32
    gemm_kernel<1><<<g_prj, 256>>>(nullptr, w_proj, b_proj, out);
}

// round 3
// speedup vs baseline: 4.7683x; 4.1160x over previous
#include <cuda_runtime.h>
#include <math.h>

#define Bq 2
#define Nn 2048
#define Cc 1024
#define Hh 16
#define Dd 64

// Scratch layouts:
//   g_q : [b][h][n][d]  natural, pre-scaled by 0.125
//   g_k : [b][h][d][n]  TRANSPOSED (feeds S-mma B operand directly)
//   g_v : [b][h][n][d]  natural
//   g_ao: [b][h][n][d]  natural (== [B,N,C] reshape for proj)
__device__ float g_q [(size_t)Bq*Hh*Nn*Dd];
__device__ float g_k [(size_t)Bq*Hh*Nn*Dd];
__device__ float g_v [(size_t)Bq*Hh*Nn*Dd];
__device__ float g_ao[(size_t)Bq*Hh*Nn*Dd];

__device__ __forceinline__ unsigned f2tf(float x) {
    unsigned u;
    asm("cvt.rna.tf32.f32 %0, %1;" : "=r"(u) : "f"(x));
    return u;
}

__device__ __forceinline__ void mma_tf32(float c[4],
                                         unsigned a0, unsigned a1, unsigned a2, unsigned a3,
                                         unsigned b0, unsigned b1) {
    asm volatile(
        "mma.sync.aligned.m16n8k8.row.col.f32.tf32.tf32.f32 "
        "{%0,%1,%2,%3}, {%4,%5,%6,%7}, {%8,%9}, {%0,%1,%2,%3};"
        : "+f"(c[0]), "+f"(c[1]), "+f"(c[2]), "+f"(c[3])
        : "r"(a0), "r"(a1), "r"(a2), "r"(a3), "r"(b0), "r"(b1));
}

// ---------------------------------------------------------------------------
// tf32 GEMM: out[M,NC] = A[M,K] @ W[NC,K]^T + bias
// 128x128x16 tile, 256 thr = 8 warps, warp tile 64x32 (4 mf x 4 nf).
// MODE 0: scatter epilogue -> g_q (scaled) / g_k (transposed) / g_v
// MODE 1: writes d_out
// ---------------------------------------------------------------------------
template<int MODE>
__global__ __launch_bounds__(256, 2)
void gemm_kernel(const float* __restrict__ Ain, const float* __restrict__ W,
                 const float* __restrict__ bias, float* __restrict__ out)
{
    constexpr int K = 1024;
    const float* A = (MODE == 0) ? Ain : g_ao;

    __shared__ unsigned As[16 * 136];   // [k][m], pad 8
    __shared__ unsigned Bs[16 * 136];   // [k][n], pad 8

    const int tid    = threadIdx.x;
    const int warp   = tid >> 5;
    const int lane   = tid & 31;
    const int t      = lane & 3;        // thread-in-group
    const int g      = lane >> 2;       // group id
    const int warp_m = warp >> 2;       // 0..1
    const int warp_n = warp & 3;        // 0..3
    const int mb     = warp_m * 64;
    const int nb     = warp_n * 32;

    const int rowBase = blockIdx.y * 128;
    const int colBase = blockIdx.x * 128;

    float c[4][4][4];                   // [mf][nf][reg]
    #pragma unroll
    for (int i = 0; i < 4; i++)
        #pragma unroll
        for (int j = 0; j < 4; j++)
            #pragma unroll
            for (int r = 0; r < 4; r++) c[i][j][r] = 0.f;

    for (int kt = 0; kt < K; kt += 16) {
        #pragma unroll
        for (int i = tid; i < 512; i += 256) {
            int r = i >> 2, c4 = i & 3;
            float4 v = *(const float4*)(A + (size_t)(rowBase + r) * K + kt + c4 * 4);
            As[(c4*4+0)*136 + r] = f2tf(v.x); As[(c4*4+1)*136 + r] = f2tf(v.y);
            As[(c4*4+2)*136 + r] = f2tf(v.z); As[(c4*4+3)*136 + r] = f2tf(v.w);
        }
        #pragma unroll
        for (int i = tid; i < 512; i += 256) {
            int r = i >> 2, c4 = i & 3;
            float4 v = *(const float4*)(W + (size_t)(colBase + r) * K + kt + c4 * 4);
            Bs[(c4*4+0)*136 + r] = f2tf(v.x); Bs[(c4*4+1)*136 + r] = f2tf(v.y);
            Bs[(c4*4+2)*136 + r] = f2tf(v.z); Bs[(c4*4+3)*136 + r] = f2tf(v.w);
        }
        __syncthreads();

        #pragma unroll
        for (int ks = 0; ks < 16; ks += 8) {
            unsigned a[4][4], b[4][2];
            #pragma unroll
            for (int mf = 0; mf < 4; mf++) {
                int m0 = mb + mf * 16;
                a[mf][0] = As[(ks+t  )*136 + m0 + g    ];
                a[mf][1] = As[(ks+t  )*136 + m0 + g + 8];
                a[mf][2] = As[(ks+t+4)*136 + m0 + g    ];
                a[mf][3] = As[(ks+t+4)*136 + m0 + g + 8];
            }
            #pragma unroll
            for (int nf = 0; nf < 4; nf++) {
                int n0 = nb + nf * 8;
                b[nf][0] = Bs[(ks+t  )*136 + n0 + g];
                b[nf][1] = Bs[(ks+t+4)*136 + n0 + g];
            }
            #pragma unroll
            for (int mf = 0; mf < 4; mf++)
                #pragma unroll
                for (int nf = 0; nf < 4; nf++)
                    mma_tf32(c[mf][nf], a[mf][0], a[mf][1], a[mf][2], a[mf][3],
                             b[nf][0], b[nf][1]);
        }
        __syncthreads();
    }

    // Epilogue
    #pragma unroll
    for (int mf = 0; mf < 4; mf++) {
        #pragma unroll
        for (int nf = 0; nf < 4; nf++) {
            #pragma unroll
            for (int half = 0; half < 2; half++) {
                int row = rowBase + mb + mf*16 + g + half*8;
                float v0 = c[mf][nf][half*2+0];
                float v1 = c[mf][nf][half*2+1];
                int col  = colBase + nb + nf*8 + t*2;
                float b0 = bias[col], b1 = bias[col+1];
                if (MODE == 0) {
                    int s = col >> 10, h = (col >> 6) & 15, d = col & 63;
                    int bb = row >> 11, n = row & 2047;
                    if (s == 0) {
                        float* p = g_q + (((size_t)bb*Hh + h)*Nn + n)*Dd + d;
                        p[0] = (v0 + b0) * 0.125f; p[1] = (v1 + b1) * 0.125f;
                    } else if (s == 1) {
                        float* p = g_k + (((size_t)bb*Hh + h)*Dd + d)*Nn + n;
                        p[0] = v0 + b0; p[Nn] = v1 + b1;
                    } else {
                        float* p = g_v + (((size_t)bb*Hh + h)*Nn + n)*Dd + d;
                        p[0] = v0 + b0; p[1] = v1 + b1;
                    }
                } else {
                    float2 o = make_float2(v0 + b0, v1 + b1);
                    *(float2*)(out + (size_t)row * 1024 + col) = o;
                }
            }
        }
    }
}

// ---------------------------------------------------------------------------
// tf32 flash attention (causal). Block = 64 queries x one (b,h), 128 threads
// (4 warps x 16 rows). Q frags in registers. K/V tiles (64 keys) in smem as
// tf32. P overlays the K buffer. Online softmax with width-4 shuffles.
// ---------------------------------------------------------------------------
__global__ __launch_bounds__(128)
void attn_kernel()
{
    __shared__ unsigned KtP[64 * 72];   // Kt[d][j] stride 72; later Ps[q][j] stride 68
    __shared__ unsigned Vs [64 * 72];   // Vs[j][d] stride 72

    const int bh   = blockIdx.x;
    const int r0   = ((int)gridDim.y - 1 - (int)blockIdx.y) * 64;  // heavy first
    const int tid  = threadIdx.x;
    const int w    = tid >> 5;
    const int lane = tid & 31;
    const int t    = lane & 3;
    const int g    = lane >> 2;
    const int wq   = w * 16;            // warp's first row within block

    const float* qb = g_q + (size_t)bh * Nn * Dd;   // [n][d], pre-scaled
    const float* kT = g_k + (size_t)bh * Nn * Dd;   // [d][n]
    const float* vb = g_v + (size_t)bh * Nn * Dd;   // [n][d]

    // Q fragments in registers: rows (r0+wq+g, +8), cols ks*8 + t (+4)
    unsigned qa[8][4];
    {
        const int row0 = r0 + wq + g, row1 = row0 + 8;
        #pragma unroll
        for (int ks = 0; ks < 8; ks++) {
            int col = ks * 8 + t;
            qa[ks][0] = f2tf(qb[(size_t)row0*64 + col    ]);
            qa[ks][1] = f2tf(qb[(size_t)row1*64 + col    ]);
            qa[ks][2] = f2tf(qb[(size_t)row0*64 + col + 4]);
            qa[ks][3] = f2tf(qb[(size_t)row1*64 + col + 4]);
        }
    }

    float o[8][4];
    #pragma unroll
    for (int df = 0; df < 8; df++)
        #pragma unroll
        for (int r = 0; r < 4; r++) o[df][r] = 0.f;
    float m0 = -1e30f, m1 = -1e30f, l0 = 0.f, l1 = 0.f;

    const int ntiles = r0 / 64 + 1;
    for (int tt = 0; tt < ntiles; tt++) {
        const int jb = tt * 64;
        __syncthreads();
        // Load K,V tiles (tf32-converted)
        #pragma unroll
        for (int i = tid; i < 1024; i += 128) {
            int r = i >> 4, c4 = (i & 15) * 4;
            float4 kv = *(const float4*)(kT + (size_t)r * Nn + jb + c4);
            KtP[r*72 + c4 + 0] = f2tf(kv.x); KtP[r*72 + c4 + 1] = f2tf(kv.y);
            KtP[r*72 + c4 + 2] = f2tf(kv.z); KtP[r*72 + c4 + 3] = f2tf(kv.w);
            float4 vv = *(const float4*)(vb + (size_t)(jb + r) * Dd + c4);
            Vs [r*72 + c4 + 0] = f2tf(vv.x); Vs [r*72 + c4 + 1] = f2tf(vv.y);
            Vs [r*72 + c4 + 2] = f2tf(vv.z); Vs [r*72 + c4 + 3] = f2tf(vv.w);
        }
        __syncthreads();

        // S = Q @ K^T  (16 rows x 64 cols per warp)
        float s[8][4];
        #pragma unroll
        for (int nf = 0; nf < 8; nf++)
            #pragma unroll
            for (int r = 0; r < 4; r++) s[nf][r] = 0.f;

        #pragma unroll
        for (int ks = 0; ks < 8; ks++) {
            int kr0 = (ks*8 + t) * 72, kr1 = (ks*8 + t + 4) * 72;
            #pragma unroll
            for (int nf = 0; nf < 8; nf++) {
                unsigned b0 = KtP[kr0 + nf*8 + g];
                unsigned b1 = KtP[kr1 + nf*8 + g];
                mma_tf32(s[nf], qa[ks][0], qa[ks][1], qa[ks][2], qa[ks][3], b0, b1);
            }
        }

        // Causal mask on the diagonal tile
        if (tt == ntiles - 1) {
            int row0 = r0 + wq + g, row1 = row0 + 8;
            #pragma unroll
            for (int nf = 0; nf < 8; nf++) {
                int c0 = jb + nf*8 + t*2, c1 = c0 + 1;
                if (c0 > row0) s[nf][0] = -1e30f;
                if (c1 > row0) s[nf][1] = -1e30f;
                if (c0 > row1) s[nf][2] = -1e30f;
                if (c1 > row1) s[nf][3] = -1e30f;
            }
        }

        // Online softmax (rows g and g+8; reduce over the 4 lanes of a group)
        float rm0 = -1e30f, rm1 = -1e30f;
        #pragma unroll
        for (int nf = 0; nf < 8; nf++) {
            rm0 = fmaxf(rm0, fmaxf(s[nf][0], s[nf][1]));
            rm1 = fmaxf(rm1, fmaxf(s[nf][2], s[nf][3]));
        }
        #pragma unroll
        for (int off = 1; off < 4; off <<= 1) {
            rm0 = fmaxf(rm0, __shfl_xor_sync(0xffffffffu, rm0, off));
            rm1 = fmaxf(rm1, __shfl_xor_sync(0xffffffffu, rm1, off));
        }
        float nm0 = fmaxf(m0, rm0), nm1 = fmaxf(m1, rm1);
        float al0 = __expf(m0 - nm0), al1 = __expf(m1 - nm1);
        m0 = nm0; m1 = nm1;
        float rs0 = 0.f, rs1 = 0.f;
        #pragma unroll
        for (int nf = 0; nf < 8; nf++) {
            s[nf][0] = __expf(s[nf][0] - nm0); rs0 += s[nf][0];
            s[nf][1] = __expf(s[nf][1] - nm0); rs0 += s[nf][1];
            s[nf][2] = __expf(s[nf][2] - nm1); rs1 += s[nf][2];
            s[nf][3] = __expf(s[nf][3] - nm1); rs1 += s[nf][3];
        }
        #pragma unroll
        for (int off = 1; off < 4; off <<= 1) {
            rs0 += __shfl_xor_sync(0xffffffffu, rs0, off);
            rs1 += __shfl_xor_sync(0xffffffffu, rs1, off);
        }
        l0 = l0 * al0 + rs0; l1 = l1 * al1 + rs1;
        #pragma unroll
        for (int df = 0; df < 8; df++) {
            o[df][0] *= al0; o[df][1] *= al0;
            o[df][2] *= al1; o[df][3] *= al1;
        }

        __syncthreads();   // all K reads done; KtP becomes Ps (stride 68)
        #pragma unroll
        for (int nf = 0; nf < 8; nf++) {
            int jc = nf*8 + t*2;
            uint2 p0 = make_uint2(f2tf(s[nf][0]), f2tf(s[nf][1]));
            uint2 p1 = make_uint2(f2tf(s[nf][2]), f2tf(s[nf][3]));
            *(uint2*)&KtP[(wq + g    )*68 + jc] = p0;
            *(uint2*)&KtP[(wq + g + 8)*68 + jc] = p1;
        }
        __syncwarp();      // warp reads only its own rows of Ps

        // O += P @ V
        #pragma unroll
        for (int ks = 0; ks < 8; ks++) {
            unsigned pa0 = KtP[(wq + g    )*68 + ks*8 + t    ];
            unsigned pa1 = KtP[(wq + g + 8)*68 + ks*8 + t    ];
            unsigned pa2 = KtP[(wq + g    )*68 + ks*8 + t + 4];
            unsigned pa3 = KtP[(wq + g + 8)*68 + ks*8 + t + 4];
            int vr0 = (ks*8 + t) * 72, vr1 = (ks*8 + t + 4) * 72;
            #pragma unroll
            for (int df = 0; df < 8; df++) {
                unsigned b0 = Vs[vr0 + df*8 + g];
                unsigned b1 = Vs[vr1 + df*8 + g];
                mma_tf32(o[df], pa0, pa1, pa2, pa3, b0, b1);
            }
        }
    }

    // Normalize + store [b][h][n][d]
    const float inv0 = 1.f / l0, inv1 = 1.f / l1;
    const int row0 = r0 + wq + g, row1 = row0 + 8;
    #pragma unroll
    for (int df = 0; df < 8; df++) {
        int dc = df*8 + t*2;
        *(float2*)(g_ao + ((size_t)bh*Nn + row0)*Dd + dc) =
            make_float2(o[df][0]*inv0, o[df][1]*inv0);
        *(float2*)(g_ao + ((size_t)bh*Nn + row1)*Dd + dc) =
            make_float2(o[df][2]*inv1, o[df][3]*inv1);
    }
}

// ---------------------------------------------------------------------------
extern "C" void kernel_launch(void* const* d_in, const int* in_sizes, int n_in,
                              void* d_out, int out_size)
{
    const float* x      = (const float*)d_in[0];
    // d_in[1] = attention_mask: exactly causal tril, encoded in-kernel — unused
    const float* w_qkv  = (const float*)d_in[2];
    const float* b_qkv  = (const float*)d_in[3];
    const float* w_proj = (const float*)d_in[4];
    const float* b_proj = (const float*)d_in[5];
    float* out = (float*)d_out;

    dim3 g_qkv(3072 / 128, (Bq * Nn) / 128);      // 24 x 32
    gemm_kernel<0><<<g_qkv, 256>>>(x, w_qkv, b_qkv, nullptr);

    dim3 g_att(Bq * Hh, Nn / 64);                 // 32 x 32
    attn_kernel<<<g_att, 128>>>();

    dim3 g_prj(1024 / 128, (Bq * Nn) / 128);      // 8 x 32
    gemm_kernel<1><<<g_prj, 256>>>(nullptr, w_proj, b_proj, out);
}

// round 4
// speedup vs baseline: 6.0762x; 1.2743x over previous
#include <cuda_runtime.h>
#include <math.h>

#define Bq 2
#define Nn 2048
#define Cc 1024
#define Hh 16
#define Dd 64

// Scratch layouts:
//   g_q : [b][h][n][d]  natural, pre-scaled by 0.125
//   g_k : [b][h][d][n]  TRANSPOSED (feeds S-mma B operand directly)
//   g_v : [b][h][n][d]  natural
//   g_ao: [b][h][n][d]  natural (== [B,N,C] reshape for proj)
__device__ float g_q [(size_t)Bq*Hh*Nn*Dd];
__device__ float g_k [(size_t)Bq*Hh*Nn*Dd];
__device__ float g_v [(size_t)Bq*Hh*Nn*Dd];
__device__ float g_ao[(size_t)Bq*Hh*Nn*Dd];

__device__ __forceinline__ unsigned f2tf(float x) {
    unsigned u;
    asm("cvt.rna.tf32.f32 %0, %1;" : "=r"(u) : "f"(x));
    return u;
}

__device__ __forceinline__ void mma_tf32(float c[4],
                                         unsigned a0, unsigned a1, unsigned a2, unsigned a3,
                                         unsigned b0, unsigned b1) {
    asm volatile(
        "mma.sync.aligned.m16n8k8.row.col.f32.tf32.tf32.f32 "
        "{%0,%1,%2,%3}, {%4,%5,%6,%7}, {%8,%9}, {%0,%1,%2,%3};"
        : "+f"(c[0]), "+f"(c[1]), "+f"(c[2]), "+f"(c[3])
        : "r"(a0), "r"(a1), "r"(a2), "r"(a3), "r"(b0), "r"(b1));
}

__device__ __forceinline__ unsigned smem_u32(const void* p) {
    return (unsigned)__cvta_generic_to_shared(p);
}
__device__ __forceinline__ void cp16(void* dst_smem, const void* src_gmem) {
    asm volatile("cp.async.cg.shared.global [%0], [%1], 16;"
                 :: "r"(smem_u32(dst_smem)), "l"(src_gmem));
}
__device__ __forceinline__ void cp_commit() {
    asm volatile("cp.async.commit_group;");
}
template<int N>
__device__ __forceinline__ void cp_wait() {
    asm volatile("cp.async.wait_group %0;" :: "n"(N));
}

// ---------------------------------------------------------------------------
// tf32 GEMM, cp.async double-buffered: out[M,NC] = A[M,K] @ W[NC,K]^T + bias
// 128x128x16 tile, 256 thr = 8 warps, warp tile 64x32.
// Raw f32 smem [row][16+4pad]; tf32 conversion at fragment load.
// MODE 0: scatter epilogue -> g_q (scaled) / g_k (transposed) / g_v
// MODE 1: writes d_out
// ---------------------------------------------------------------------------
#define RS 20   // smem row stride in floats (16 data + 4 pad)

template<int MODE>
__global__ __launch_bounds__(256, 2)
void gemm_kernel(const float* __restrict__ Ain, const float* __restrict__ W,
                 const float* __restrict__ bias, float* __restrict__ out)
{
    constexpr int K = 1024;
    constexpr int NT = K / 16;          // 64 k-tiles
    const float* A = (MODE == 0) ? Ain : g_ao;

    __shared__ float As[2][128 * RS];
    __shared__ float Bs[2][128 * RS];

    const int tid    = threadIdx.x;
    const int warp   = tid >> 5;
    const int lane   = tid & 31;
    const int t      = lane & 3;
    const int g      = lane >> 2;
    const int mb     = (warp >> 2) * 64;
    const int nb     = (warp & 3) * 32;

    const int rowBase = blockIdx.y * 128;
    const int colBase = blockIdx.x * 128;

    // staging: 512 16B-chunks per matrix per tile; thread does chunks tid, tid+256
    const int sr0 = tid >> 2,          sc0 = (tid & 3) * 4;        // row, col(floats)
    const int sr1 = (tid + 256) >> 2,  sc1 = ((tid + 256) & 3) * 4;

    auto stage = [&](int buf, int kt) {
        cp16(&As[buf][sr0 * RS + sc0], A + (size_t)(rowBase + sr0) * K + kt + sc0);
        cp16(&As[buf][sr1 * RS + sc1], A + (size_t)(rowBase + sr1) * K + kt + sc1);
        cp16(&Bs[buf][sr0 * RS + sc0], W + (size_t)(colBase + sr0) * K + kt + sc0);
        cp16(&Bs[buf][sr1 * RS + sc1], W + (size_t)(colBase + sr1) * K + kt + sc1);
        cp_commit();
    };

    float c[4][4][4];
    #pragma unroll
    for (int i = 0; i < 4; i++)
        #pragma unroll
        for (int j = 0; j < 4; j++)
            #pragma unroll
            for (int r = 0; r < 4; r++) c[i][j][r] = 0.f;

    stage(0, 0);

    for (int tt = 0; tt < NT; tt++) {
        if (tt + 1 < NT) { stage((tt + 1) & 1, (tt + 1) * 16); cp_wait<1>(); }
        else             { cp_wait<0>(); }
        __syncthreads();

        const float* as = As[tt & 1];
        const float* bs = Bs[tt & 1];

        #pragma unroll
        for (int ks = 0; ks < 16; ks += 8) {
            unsigned a[4][4], b[4][2];
            #pragma unroll
            for (int mf = 0; mf < 4; mf++) {
                const float* ar = as + (mb + mf * 16 + g) * RS + ks + t;
                a[mf][0] = f2tf(ar[0]);
                a[mf][2] = f2tf(ar[4]);
                a[mf][1] = f2tf(ar[8 * RS]);
                a[mf][3] = f2tf(ar[8 * RS + 4]);
            }
            #pragma unroll
            for (int nf = 0; nf < 4; nf++) {
                const float* br = bs + (nb + nf * 8 + g) * RS + ks + t;
                b[nf][0] = f2tf(br[0]);
                b[nf][1] = f2tf(br[4]);
            }
            #pragma unroll
            for (int mf = 0; mf < 4; mf++)
                #pragma unroll
                for (int nf = 0; nf < 4; nf++)
                    mma_tf32(c[mf][nf], a[mf][0], a[mf][1], a[mf][2], a[mf][3],
                             b[nf][0], b[nf][1]);
        }
        __syncthreads();
    }

    // Epilogue
    #pragma unroll
    for (int mf = 0; mf < 4; mf++) {
        #pragma unroll
        for (int nf = 0; nf < 4; nf++) {
            #pragma unroll
            for (int half = 0; half < 2; half++) {
                int row = rowBase + mb + mf*16 + g + half*8;
                float v0 = c[mf][nf][half*2+0];
                float v1 = c[mf][nf][half*2+1];
                int col  = colBase + nb + nf*8 + t*2;
                float b0 = bias[col], b1 = bias[col+1];
                if (MODE == 0) {
                    int s = col >> 10, h = (col >> 6) & 15, d = col & 63;
                    int bb = row >> 11, n = row & 2047;
                    if (s == 0) {
                        float* p = g_q + (((size_t)bb*Hh + h)*Nn + n)*Dd + d;
                        p[0] = (v0 + b0) * 0.125f; p[1] = (v1 + b1) * 0.125f;
                    } else if (s == 1) {
                        float* p = g_k + (((size_t)bb*Hh + h)*Dd + d)*Nn + n;
                        p[0] = v0 + b0; p[Nn] = v1 + b1;
                    } else {
                        float* p = g_v + (((size_t)bb*Hh + h)*Nn + n)*Dd + d;
                        p[0] = v0 + b0; p[1] = v1 + b1;
                    }
                } else {
                    float2 o = make_float2(v0 + b0, v1 + b1);
                    *(float2*)(out + (size_t)row * 1024 + col) = o;
                }
            }
        }
    }
}

// ---------------------------------------------------------------------------
// tf32 flash attention (causal). Block = 64 queries x one (b,h), 128 threads
// (4 warps x 16 rows). Q frags in registers. K/V tiles (64 keys) in smem as
// tf32. P overlays the K buffer. Online softmax with width-4 shuffles.
// ---------------------------------------------------------------------------
__global__ __launch_bounds__(128)
void attn_kernel()
{
    __shared__ unsigned KtP[64 * 72];   // Kt[d][j] stride 72; later Ps[q][j] stride 68
    __shared__ unsigned Vs [64 * 72];   // Vs[j][d] stride 72

    const int bh   = blockIdx.x;
    const int r0   = ((int)gridDim.y - 1 - (int)blockIdx.y) * 64;  // heavy first
    const int tid  = threadIdx.x;
    const int w    = tid >> 5;
    const int lane = tid & 31;
    const int t    = lane & 3;
    const int g    = lane >> 2;
    const int wq   = w * 16;

    const float* qb = g_q + (size_t)bh * Nn * Dd;   // [n][d], pre-scaled
    const float* kT = g_k + (size_t)bh * Nn * Dd;   // [d][n]
    const float* vb = g_v + (size_t)bh * Nn * Dd;   // [n][d]

    unsigned qa[8][4];
    {
        const int row0 = r0 + wq + g, row1 = row0 + 8;
        #pragma unroll
        for (int ks = 0; ks < 8; ks++) {
            int col = ks * 8 + t;
            qa[ks][0] = f2tf(qb[(size_t)row0*64 + col    ]);
            qa[ks][1] = f2tf(qb[(size_t)row1*64 + col    ]);
            qa[ks][2] = f2tf(qb[(size_t)row0*64 + col + 4]);
            qa[ks][3] = f2tf(qb[(size_t)row1*64 + col + 4]);
        }
    }

    float o[8][4];
    #pragma unroll
    for (int df = 0; df < 8; df++)
        #pragma unroll
        for (int r = 0; r < 4; r++) o[df][r] = 0.f;
    float m0 = -1e30f, m1 = -1e30f, l0 = 0.f, l1 = 0.f;

    const int ntiles = r0 / 64 + 1;
    for (int tt = 0; tt < ntiles; tt++) {
        const int jb = tt * 64;
        __syncthreads();
        #pragma unroll
        for (int i = tid; i < 1024; i += 128) {
            int r = i >> 4, c4 = (i & 15) * 4;
            float4 kv = *(const float4*)(kT + (size_t)r * Nn + jb + c4);
            KtP[r*72 + c4 + 0] = f2tf(kv.x); KtP[r*72 + c4 + 1] = f2tf(kv.y);
            KtP[r*72 + c4 + 2] = f2tf(kv.z); KtP[r*72 + c4 + 3] = f2tf(kv.w);
            float4 vv = *(const float4*)(vb + (size_t)(jb + r) * Dd + c4);
            Vs [r*72 + c4 + 0] = f2tf(vv.x); Vs [r*72 + c4 + 1] = f2tf(vv.y);
            Vs [r*72 + c4 + 2] = f2tf(vv.z); Vs [r*72 + c4 + 3] = f2tf(vv.w);
        }
        __syncthreads();

        float s[8][4];
        #pragma unroll
        for (int nf = 0; nf < 8; nf++)
            #pragma unroll
            for (int r = 0; r < 4; r++) s[nf][r] = 0.f;

        #pragma unroll
        for (int ks = 0; ks < 8; ks++) {
            int kr0 = (ks*8 + t) * 72, kr1 = (ks*8 + t + 4) * 72;
            #pragma unroll
            for (int nf = 0; nf < 8; nf++) {
                unsigned b0 = KtP[kr0 + nf*8 + g];
                unsigned b1 = KtP[kr1 + nf*8 + g];
                mma_tf32(s[nf], qa[ks][0], qa[ks][1], qa[ks][2], qa[ks][3], b0, b1);
            }
        }

        if (tt == ntiles - 1) {
            int row0 = r0 + wq + g, row1 = row0 + 8;
            #pragma unroll
            for (int nf = 0; nf < 8; nf++) {
                int c0 = jb + nf*8 + t*2, c1 = c0 + 1;
                if (c0 > row0) s[nf][0] = -1e30f;
                if (c1 > row0) s[nf][1] = -1e30f;
                if (c0 > row1) s[nf][2] = -1e30f;
                if (c1 > row1) s[nf][3] = -1e30f;
            }
        }

        float rm0 = -1e30f, rm1 = -1e30f;
        #pragma unroll
        for (int nf = 0; nf < 8; nf++) {
            rm0 = fmaxf(rm0, fmaxf(s[nf][0], s[nf][1]));
            rm1 = fmaxf(rm1, fmaxf(s[nf][2], s[nf][3]));
        }
        #pragma unroll
        for (int off = 1; off < 4; off <<= 1) {
            rm0 = fmaxf(rm0, __shfl_xor_sync(0xffffffffu, rm0, off));
            rm1 = fmaxf(rm1, __shfl_xor_sync(0xffffffffu, rm1, off));
        }
        float nm0 = fmaxf(m0, rm0), nm1 = fmaxf(m1, rm1);
        float al0 = __expf(m0 - nm0), al1 = __expf(m1 - nm1);
        m0 = nm0; m1 = nm1;
        float rs0 = 0.f, rs1 = 0.f;
        #pragma unroll
        for (int nf = 0; nf < 8; nf++) {
            s[nf][0] = __expf(s[nf][0] - nm0); rs0 += s[nf][0];
            s[nf][1] = __expf(s[nf][1] - nm0); rs0 += s[nf][1];
            s[nf][2] = __expf(s[nf][2] - nm1); rs1 += s[nf][2];
            s[nf][3] = __expf(s[nf][3] - nm1); rs1 += s[nf][3];
        }
        #pragma unroll
        for (int off = 1; off < 4; off <<= 1) {
            rs0 += __shfl_xor_sync(0xffffffffu, rs0, off);
            rs1 += __shfl_xor_sync(0xffffffffu, rs1, off);
        }
        l0 = l0 * al0 + rs0; l1 = l1 * al1 + rs1;
        #pragma unroll
        for (int df = 0; df < 8; df++) {
            o[df][0] *= al0; o[df][1] *= al0;
            o[df][2] *= al1; o[df][3] *= al1;
        }

        __syncthreads();
        #pragma unroll
        for (int nf = 0; nf < 8; nf++) {
            int jc = nf*8 + t*2;
            uint2 p0 = make_uint2(f2tf(s[nf][0]), f2tf(s[nf][1]));
            uint2 p1 = make_uint2(f2tf(s[nf][2]), f2tf(s[nf][3]));
            *(uint2*)&KtP[(wq + g    )*68 + jc] = p0;
            *(uint2*)&KtP[(wq + g + 8)*68 + jc] = p1;
        }
        __syncwarp();

        #pragma unroll
        for (int ks = 0; ks < 8; ks++) {
            unsigned pa0 = KtP[(wq + g    )*68 + ks*8 + t    ];
            unsigned pa1 = KtP[(wq + g + 8)*68 + ks*8 + t    ];
            unsigned pa2 = KtP[(wq + g    )*68 + ks*8 + t + 4];
            unsigned pa3 = KtP[(wq + g + 8)*68 + ks*8 + t + 4];
            int vr0 = (ks*8 + t) * 72, vr1 = (ks*8 + t + 4) * 72;
            #pragma unroll
            for (int df = 0; df < 8; df++) {
                unsigned b0 = Vs[vr0 + df*8 + g];
                unsigned b1 = Vs[vr1 + df*8 + g];
                mma_tf32(o[df], pa0, pa1, pa2, pa3, b0, b1);
            }
        }
    }

    const float inv0 = 1.f / l0, inv1 = 1.f / l1;
    const int row0 = r0 + wq + g, row1 = row0 + 8;
    #pragma unroll
    for (int df = 0; df < 8; df++) {
        int dc = df*8 + t*2;
        *(float2*)(g_ao + ((size_t)bh*Nn + row0)*Dd + dc) =
            make_float2(o[df][0]*inv0, o[df][1]*inv0);
        *(float2*)(g_ao + ((size_t)bh*Nn + row1)*Dd + dc) =
            make_float2(o[df][2]*inv1, o[df][3]*inv1);
    }
}

// ---------------------------------------------------------------------------
extern "C" void kernel_launch(void* const* d_in, const int* in_sizes, int n_in,
                              void* d_out, int out_size)
{
    const float* x      = (const float*)d_in[0];
    // d_in[1] = attention_mask: exactly causal tril, encoded in-kernel — unused
    const float* w_qkv  = (const float*)d_in[2];
    const float* b_qkv  = (const float*)d_in[3];
    const float* w_proj = (const float*)d_in[4];
    const float* b_proj = (const float*)d_in[5];
    float* out = (float*)d_out;

    dim3 g_qkv(3072 / 128, (Bq * Nn) / 128);      // 24 x 32
    gemm_kernel<0><<<g_qkv, 256>>>(x, w_qkv, b_qkv, nullptr);

    dim3 g_att(Bq * Hh, Nn / 64);                 // 32 x 32
    attn_kernel<<<g_att, 128>>>();

    dim3 g_prj(1024 / 128, (Bq * Nn) / 128);      // 8 x 32
    gemm_kernel<1><<<g_prj, 256>>>(nullptr, w_proj, b_proj, out);
}